// round 11
// baseline (speedup 1.0000x reference)
#include <cuda_runtime.h>
#include <cstdint>

#define BQ     32
#define NKEYS  4096
#define DIM    64
#define NQ     8
#define CPB    32         // chunks per batch -> grid 1024
#define CHUNK  128        // keys per CTA (4 warps x 32)
#define WKEYS  32         // keys per warp; lane = key
#define PROW   16         // floats per splatted-P row

typedef unsigned long long u64;

// ---- global scratch ----
__device__ float    g_pv[BQ * CPB * NQ * DIM];
__device__ float    g_cs[BQ * CPB * NQ];
__device__ unsigned g_cnt[BQ];

// ---- cp.async ----
__device__ __forceinline__ void cp16(uint32_t s, const float* g) {
    asm volatile("cp.async.cg.shared.global [%0], [%1], 16;\n" :: "r"(s), "l"(g));
}
__device__ __forceinline__ void cp_commit() {
    asm volatile("cp.async.commit_group;\n" ::: "memory");
}
template <int N>
__device__ __forceinline__ void cp_wait() {
    asm volatile("cp.async.wait_group %0;\n" :: "n"(N) : "memory");
}

// ---- packed f32x2 ----
__device__ __forceinline__ void fma2(u64& d, u64 a, u64 b) {
    asm("fma.rn.f32x2 %0, %1, %2, %0;" : "+l"(d) : "l"(a), "l"(b));
}
__device__ __forceinline__ float f2lo(u64 x) { return __uint_as_float((unsigned)x); }
__device__ __forceinline__ float f2hi(u64 x) { return __uint_as_float((unsigned)(x >> 32)); }
__device__ __forceinline__ u64 splat2(float p) {
    u64 r; asm("mov.b64 %0, {%1, %1};" : "=l"(r) : "f"(p)); return r;
}

// ---- smem layout (float offsets) ----
// Q (prescaled): 8 x 64 = 512 floats at 0 (uniform reads)
// per-warp: KH0 (32 keys x 32 floats, chunk-swizzled, 1024) | KH1 (1024) | P (32x16 = 512)
//   KH0/KH1 reused as V buffers (keys 0-15 / 16-31, row 64) during PV;
//   KH0 reused again as epilogue reduction area.
#define W_KH0   0
#define W_KH1   1024
#define W_P     2048
#define W_SZ    2560
#define OFF_Q   0
#define OFF_W(w) (512 + (w) * W_SZ)
#define SMEM_FLOATS (512 + 4 * W_SZ)           // 10752 floats = 43,008 B -> 5 CTAs/SM

extern __shared__ float smem[];

__global__ __launch_bounds__(128, 5)
void attn_fused(const float* __restrict__ keys,
                const float* __restrict__ vals,
                const float* __restrict__ query,
                float* __restrict__ out) {
    const int tid  = threadIdx.x;
    const int lane = tid & 31;     // = this lane's key within the warp tile
    const int warp = tid >> 5;
    const int b     = blockIdx.x >> 5;
    const int chunk = blockIdx.x & 31;
    const int n0    = chunk * CHUNK;
    __shared__ int s_last;

    const uint32_t sbase = (uint32_t)__cvta_generic_to_shared(smem);
    const uint32_t wbase = sbase + (uint32_t)(OFF_W(warp) << 2);

    const float* kgp = keys + ((size_t)b * NKEYS + n0 + warp * WKEYS) * DIM;
    const float* vgp = vals + ((size_t)b * NKEYS + n0 + warp * WKEYS) * DIM;

    // ---- stage K half h (dims 32h..32h+31 of all 32 keys), swizzled slots ----
    // key k's 4-float chunk i2 stored at row k, slot (i2+k)&7  -> no padding,
    // conflict-free on both the staging STS and the lane=key LDS.128 reads.
    auto stage_k = [&](int h) {
        const uint32_t kd = wbase + (uint32_t)((h ? W_KH1 : W_KH0) << 2);
#pragma unroll
        for (int i = 0; i < 8; ++i) {
            int c = i * 32 + lane;               // 0..255
            int k = c >> 3, i2 = c & 7;
            int slot = (i2 + k) & 7;
            cp16(kd + (uint32_t)((k * 32 + slot * 4) << 2),
                 kgp + k * DIM + h * 32 + i2 * 4);
        }
        cp_commit();
    };
    // ---- stage V half h (keys 16h..16h+15, full rows) into KH buffer h ----
    auto stage_v = [&](int h) {
        const uint32_t vd = wbase + (uint32_t)((h ? W_KH1 : W_KH0) << 2);
        const float* vt = vgp + h * 16 * DIM;
#pragma unroll
        for (int i = 0; i < 8; ++i) {
            int c = i * 32 + lane;               // 0..255
            int k = c >> 4, i2 = c & 15;
            cp16(vd + (uint32_t)((k * DIM + i2 * 4) << 2),
                 vt + k * DIM + i2 * 4);
        }
        cp_commit();
    };

    stage_k(0);
    stage_k(1);

    // ---- Q into smem, prescaled by 1/8 (uniform-read layout) ----
    if (tid < 128) {
        int r = tid >> 4, s = (tid & 15) << 2;
        float4 qv = *(const float4*)(query + ((size_t)b * NQ + r) * DIM + s);
        qv.x *= 0.125f; qv.y *= 0.125f; qv.z *= 0.125f; qv.w *= 0.125f;
        *(float4*)&smem[OFF_Q + r * DIM + s] = qv;
    }
    __syncthreads();

    // ================= QK: lane = key, K distinct (swizzled), Q uniform =================
    u64 acc[8];
#pragma unroll
    for (int m = 0; m < 8; ++m) acc[m] = 0ull;

    const float* Kr0 = &smem[OFF_W(warp) + W_KH0 + lane * 32];
    const float* Kr1 = &smem[OFF_W(warp) + W_KH1 + lane * 32];

    cp_wait<1>();  __syncwarp();          // KH0 ready
#pragma unroll
    for (int i = 0; i < 8; ++i) {         // dims 0..31, chunk i at slot (i+lane)&7
        ulonglong2 kc = *(const ulonglong2*)(Kr0 + (((i + lane) & 7) << 2));
#pragma unroll
        for (int m = 0; m < 8; ++m) {
            ulonglong2 qc = *(const ulonglong2*)&smem[OFF_Q + m * DIM + i * 4];
            fma2(acc[m], kc.x, qc.x);
            fma2(acc[m], kc.y, qc.y);
        }
    }
    stage_v(0);                            // KH0 consumed -> refill with V keys 0-15

    cp_wait<1>();  __syncwarp();          // KH1 ready (Vh0 pending)
#pragma unroll
    for (int i = 0; i < 8; ++i) {         // dims 32..63
        ulonglong2 kc = *(const ulonglong2*)(Kr1 + (((i + lane) & 7) << 2));
#pragma unroll
        for (int m = 0; m < 8; ++m) {
            ulonglong2 qc = *(const ulonglong2*)&smem[OFF_Q + m * DIM + 32 + i * 4];
            fma2(acc[m], kc.x, qc.x);
            fma2(acc[m], kc.y, qc.y);
        }
    }
    stage_v(1);                            // KH1 consumed -> refill with V keys 16-31

    // ================= softmax: fully lane-local, no shuffles =================
    {
        float e0 = __expf(f2lo(acc[0]) + f2hi(acc[0]));
        float e1 = __expf(f2lo(acc[1]) + f2hi(acc[1]));
        float e2 = __expf(f2lo(acc[2]) + f2hi(acc[2]));
        float e3 = __expf(f2lo(acc[3]) + f2hi(acc[3]));
        float e4 = __expf(f2lo(acc[4]) + f2hi(acc[4]));
        float e5 = __expf(f2lo(acc[5]) + f2hi(acc[5]));
        float e6 = __expf(f2lo(acc[6]) + f2hi(acc[6]));
        float e7 = __expf(f2lo(acc[7]) + f2hi(acc[7]));
        float sum = ((e0 + e1) + (e2 + e3)) + ((e4 + e5) + (e6 + e7));
        float inv = __fdividef(1.0f, sum);
        float* Pr = &smem[OFF_W(warp) + W_P + lane * PROW];
        u64 pp0 = splat2(fmaf(e0, inv, 1e-8f)), pp1 = splat2(fmaf(e1, inv, 1e-8f));
        u64 pp2 = splat2(fmaf(e2, inv, 1e-8f)), pp3 = splat2(fmaf(e3, inv, 1e-8f));
        u64 pp4 = splat2(fmaf(e4, inv, 1e-8f)), pp5 = splat2(fmaf(e5, inv, 1e-8f));
        u64 pp6 = splat2(fmaf(e6, inv, 1e-8f)), pp7 = splat2(fmaf(e7, inv, 1e-8f));
        ulonglong2* Pq = (ulonglong2*)Pr;
        Pq[0] = make_ulonglong2(pp0, pp1);
        Pq[1] = make_ulonglong2(pp2, pp3);
        Pq[2] = make_ulonglong2(pp4, pp5);
        Pq[3] = make_ulonglong2(pp6, pp7);
    }
    __syncwarp();                          // P visible to all lanes

    // ================= PV: p uniform, V distinct (lane = dim pair) =================
    u64 pv[8];
#pragma unroll
    for (int m = 0; m < 8; ++m) pv[m] = 0ull;

    const float* Pbase = &smem[OFF_W(warp) + W_P];
    const float* Vb0   = &smem[OFF_W(warp) + W_KH0];
    const float* Vb1   = &smem[OFF_W(warp) + W_KH1];

    cp_wait<1>();  __syncwarp();          // Vh0 landed
#pragma unroll
    for (int k = 0; k < 16; ++k) {
        const ulonglong2* Pq = (const ulonglong2*)(Pbase + k * PROW);
        ulonglong2 p01 = Pq[0], p23 = Pq[1], p45 = Pq[2], p67 = Pq[3];
        u64 v = *(const u64*)(Vb0 + k * DIM + (lane << 1));
        fma2(pv[0], p01.x, v); fma2(pv[1], p01.y, v);
        fma2(pv[2], p23.x, v); fma2(pv[3], p23.y, v);
        fma2(pv[4], p45.x, v); fma2(pv[5], p45.y, v);
        fma2(pv[6], p67.x, v); fma2(pv[7], p67.y, v);
    }
    cp_wait<0>();  __syncwarp();          // Vh1 landed
#pragma unroll
    for (int k = 0; k < 16; ++k) {
        const ulonglong2* Pq = (const ulonglong2*)(Pbase + (k + 16) * PROW);
        ulonglong2 p01 = Pq[0], p23 = Pq[1], p45 = Pq[2], p67 = Pq[3];
        u64 v = *(const u64*)(Vb1 + k * DIM + (lane << 1));
        fma2(pv[0], p01.x, v); fma2(pv[1], p01.y, v);
        fma2(pv[2], p23.x, v); fma2(pv[3], p23.y, v);
        fma2(pv[4], p45.x, v); fma2(pv[5], p45.y, v);
        fma2(pv[6], p67.x, v); fma2(pv[7], p67.y, v);
    }
    __syncwarp();

    // ================= per-warp epilogue =================
    {
        float* red = &smem[OFF_W(warp)];   // reuses KH0 region
#pragma unroll
        for (int m = 0; m < 8; ++m)
            *(u64*)&red[m * 64 + (lane << 1)] = pv[m];
        // colsum: sum splatted p (lo half) over the 32 keys, from P
        if (lane < 8) {
            float s = 0.f;
#pragma unroll
            for (int k = 0; k < 32; ++k)
                s += Pbase[k * PROW + (lane << 1)];
            red[512 + lane] = s;
        }
    }
    __syncthreads();

    const int pidx = (b * CPB + chunk) * NQ;
    if (tid < 8) {
        float s = 0.f;
#pragma unroll
        for (int w = 0; w < 4; ++w) s += smem[OFF_W(w) + 512 + tid];
        g_cs[pidx + tid] = s;
    }
    {
        int off = tid * 4;                    // 128 threads x float4 = 512 floats
        float4 s = make_float4(0.f, 0.f, 0.f, 0.f);
#pragma unroll
        for (int w = 0; w < 4; ++w) {
            float4 p = *(const float4*)&smem[OFF_W(w) + off];
            s.x += p.x; s.y += p.y; s.z += p.z; s.w += p.w;
        }
        *(float4*)&g_pv[(size_t)pidx * DIM + off] = s;
    }

    // ---- fused finalize: last chunk CTA of this batch ----
    __syncthreads();
    if (tid == 0) {
        __threadfence();
        unsigned old = atomicAdd(&g_cnt[b], 1u);
        s_last = (old == CPB - 1) ? 1 : 0;
    }
    __syncthreads();
    if (s_last) {
        __threadfence();
        int qm = tid >> 4, v4 = (tid & 15) << 2;
        float c0 = 0.f;
        float4 acc4 = make_float4(0.f, 0.f, 0.f, 0.f);
#pragma unroll
        for (int c = 0; c < CPB; ++c) {
            c0 += g_cs[(b * CPB + c) * NQ + qm];
            float4 p = *(const float4*)&g_pv[((size_t)(b * CPB + c) * NQ + qm) * DIM + v4];
            acc4.x += p.x; acc4.y += p.y; acc4.z += p.z; acc4.w += p.w;
        }
        float inv = 1.0f / c0;
        *(float4*)&out[((size_t)b * NQ + qm) * DIM + v4] =
            make_float4(acc4.x * inv, acc4.y * inv, acc4.z * inv, acc4.w * inv);
        if (tid == 0) g_cnt[b] = 0;   // reset for next graph replay
    }
}

extern "C" void kernel_launch(void* const* d_in, const int* in_sizes, int n_in,
                              void* d_out, int out_size) {
    const float* keys  = (const float*)d_in[0];
    const float* vals  = (const float*)d_in[1];
    const float* query = (const float*)d_in[2];
    float* out = (float*)d_out;

    cudaFuncSetAttribute(attn_fused,
                         cudaFuncAttributeMaxDynamicSharedMemorySize,
                         SMEM_FLOATS * sizeof(float));
    attn_fused<<<BQ * CPB, 128, SMEM_FLOATS * sizeof(float)>>>(keys, vals, query, out);
}

// round 12
// speedup vs baseline: 1.1082x; 1.1082x over previous
#include <cuda_runtime.h>
#include <cstdint>

#define BQ     32
#define NKEYS  4096
#define DIM    64
#define NQ     8
#define CPB    16         // chunks per batch -> grid 512 (one wave at 4 CTA/SM)
#define CHUNK  256        // keys per CTA (4 warps x 64)
#define WKEYS  64         // keys per warp: 2 tiles of 32, lane = key-in-tile
#define NT     2          // tiles per warp
#define KHROW  36         // floats per K half-row (32 + 4 pad) -> conflict-free
#define PROW   20         // floats per splatted-P row (16 + 4 pad)

typedef unsigned long long u64;

// ---- global scratch ----
__device__ float    g_pv[BQ * CPB * NQ * DIM];
__device__ float    g_cs[BQ * CPB * NQ];
__device__ unsigned g_cnt[BQ];

// ---- cp.async ----
__device__ __forceinline__ void cp16(uint32_t s, const float* g) {
    asm volatile("cp.async.cg.shared.global [%0], [%1], 16;\n" :: "r"(s), "l"(g));
}
__device__ __forceinline__ void cp_commit() {
    asm volatile("cp.async.commit_group;\n" ::: "memory");
}
template <int N>
__device__ __forceinline__ void cp_wait() {
    asm volatile("cp.async.wait_group %0;\n" :: "n"(N) : "memory");
}

// ---- packed f32x2 ----
__device__ __forceinline__ void fma2(u64& d, u64 a, u64 b) {
    asm("fma.rn.f32x2 %0, %1, %2, %0;" : "+l"(d) : "l"(a), "l"(b));
}
__device__ __forceinline__ float f2lo(u64 x) { return __uint_as_float((unsigned)x); }
__device__ __forceinline__ float f2hi(u64 x) { return __uint_as_float((unsigned)(x >> 32)); }
__device__ __forceinline__ u64 splat2(float p) {
    u64 r; asm("mov.b64 %0, {%1, %1};" : "=l"(r) : "f"(p)); return r;
}

// ---- smem layout (float offsets) ----
// Q (prescaled): 8 x 64 = 512 floats at 0 (uniform reads)
// per-warp region: BufA (32x36=1152) | BufB (1152) | P (32x20=640)
//   BufA/B hold K halves during QK, then V halves during PV, then next tile's K;
//   BufA reused as the epilogue reduction area at the end.
#define W_A     0
#define W_B     1152
#define W_P     2304
#define W_SZ    2944
#define OFF_Q   0
#define OFF_W(w) (512 + (w) * W_SZ)
#define SMEM_FLOATS (512 + 4 * W_SZ)           // 12288 floats = 49,152 B -> 4 CTAs/SM

extern __shared__ float smem[];

__global__ __launch_bounds__(128, 4)
void attn_fused(const float* __restrict__ keys,
                const float* __restrict__ vals,
                const float* __restrict__ query,
                float* __restrict__ out) {
    const int tid  = threadIdx.x;
    const int lane = tid & 31;     // = this lane's key within the current tile
    const int warp = tid >> 5;
    const int b     = blockIdx.x >> 4;
    const int chunk = blockIdx.x & 15;
    const int n0    = chunk * CHUNK;
    __shared__ int s_last;

    const uint32_t sbase = (uint32_t)__cvta_generic_to_shared(smem);
    const uint32_t wbase = sbase + (uint32_t)(OFF_W(warp) << 2);

    const float* kgp = keys + ((size_t)b * NKEYS + n0 + warp * WKEYS) * DIM;
    const float* vgp = vals + ((size_t)b * NKEYS + n0 + warp * WKEYS) * DIM;

    // ---- stage K half h of tile t (dims 32h..32h+31, 32 keys) into buffer h ----
    auto stage_k = [&](int t, int h) {
        const uint32_t kd = wbase + (uint32_t)((h ? W_B : W_A) << 2);
        const float* kt = kgp + t * 32 * DIM;
#pragma unroll
        for (int i = 0; i < 8; ++i) {
            int c = i * 32 + lane;               // 0..255
            int k = c >> 3, i2 = c & 7;
            cp16(kd + (uint32_t)((k * KHROW + i2 * 4) << 2),
                 kt + k * DIM + h * 32 + i2 * 4);
        }
        cp_commit();
    };
    // ---- stage V half h of tile t (keys 16h..16h+15, full rows) into buffer h ----
    auto stage_v = [&](int t, int h) {
        const uint32_t vd = wbase + (uint32_t)((h ? W_B : W_A) << 2);
        const float* vt = vgp + (t * 32 + h * 16) * DIM;
#pragma unroll
        for (int i = 0; i < 8; ++i) {
            int c = i * 32 + lane;               // 0..255
            int k = c >> 4, i2 = c & 15;
            cp16(vd + (uint32_t)((k * DIM + i2 * 4) << 2),
                 vt + k * DIM + i2 * 4);
        }
        cp_commit();
    };

    stage_k(0, 0);
    stage_k(0, 1);

    // ---- Q into smem, prescaled by 1/8 (uniform-read layout) ----
    {
        int r = tid >> 4, s = (tid & 15) << 2;
        float4 qv = *(const float4*)(query + ((size_t)b * NQ + r) * DIM + s);
        qv.x *= 0.125f; qv.y *= 0.125f; qv.z *= 0.125f; qv.w *= 0.125f;
        *(float4*)&smem[OFF_Q + r * DIM + s] = qv;
    }
    __syncthreads();

    const float* Kr0 = &smem[OFF_W(warp) + W_A + lane * KHROW];
    const float* Kr1 = &smem[OFF_W(warp) + W_B + lane * KHROW];
    const float* Pbase = &smem[OFF_W(warp) + W_P];
    const float* Vb0   = &smem[OFF_W(warp) + W_A];
    const float* Vb1   = &smem[OFF_W(warp) + W_B];

    float cs[8];
#pragma unroll
    for (int m = 0; m < 8; ++m) cs[m] = 0.f;
    u64 pv[8];
#pragma unroll
    for (int m = 0; m < 8; ++m) pv[m] = 0ull;

#pragma unroll
    for (int t = 0; t < NT; ++t) {
        // ===== QK: lane = key, K distinct (padded), Q uniform =====
        u64 acc[8];
#pragma unroll
        for (int m = 0; m < 8; ++m) acc[m] = 0ull;

        cp_wait<1>();  __syncwarp();          // K half A of tile t ready
#pragma unroll
        for (int i = 0; i < 8; ++i) {         // dims 0..31
            ulonglong2 kc = *(const ulonglong2*)(Kr0 + i * 4);
#pragma unroll
            for (int m = 0; m < 8; ++m) {
                ulonglong2 qc = *(const ulonglong2*)&smem[OFF_Q + m * DIM + i * 4];
                fma2(acc[m], kc.x, qc.x);
                fma2(acc[m], kc.y, qc.y);
            }
        }
        stage_v(t, 0);                         // A consumed -> V keys 0-15 of tile t

        cp_wait<1>();  __syncwarp();          // K half B ready
#pragma unroll
        for (int i = 0; i < 8; ++i) {         // dims 32..63
            ulonglong2 kc = *(const ulonglong2*)(Kr1 + i * 4);
#pragma unroll
            for (int m = 0; m < 8; ++m) {
                ulonglong2 qc = *(const ulonglong2*)&smem[OFF_Q + m * DIM + 32 + i * 4];
                fma2(acc[m], kc.x, qc.x);
                fma2(acc[m], kc.y, qc.y);
            }
        }
        stage_v(t, 1);                         // B consumed -> V keys 16-31 of tile t

        // ===== softmax: fully lane-local, no shuffles =====
        {
            float e0 = __expf(f2lo(acc[0]) + f2hi(acc[0]));
            float e1 = __expf(f2lo(acc[1]) + f2hi(acc[1]));
            float e2 = __expf(f2lo(acc[2]) + f2hi(acc[2]));
            float e3 = __expf(f2lo(acc[3]) + f2hi(acc[3]));
            float e4 = __expf(f2lo(acc[4]) + f2hi(acc[4]));
            float e5 = __expf(f2lo(acc[5]) + f2hi(acc[5]));
            float e6 = __expf(f2lo(acc[6]) + f2hi(acc[6]));
            float e7 = __expf(f2lo(acc[7]) + f2hi(acc[7]));
            float sum = ((e0 + e1) + (e2 + e3)) + ((e4 + e5) + (e6 + e7));
            float inv = __fdividef(1.0f, sum);
            float p0 = fmaf(e0, inv, 1e-8f), p1 = fmaf(e1, inv, 1e-8f);
            float p2 = fmaf(e2, inv, 1e-8f), p3 = fmaf(e3, inv, 1e-8f);
            float p4 = fmaf(e4, inv, 1e-8f), p5 = fmaf(e5, inv, 1e-8f);
            float p6 = fmaf(e6, inv, 1e-8f), p7 = fmaf(e7, inv, 1e-8f);
            cs[0] += p0; cs[1] += p1; cs[2] += p2; cs[3] += p3;
            cs[4] += p4; cs[5] += p5; cs[6] += p6; cs[7] += p7;
            ulonglong2* Pq = (ulonglong2*)&smem[OFF_W(warp) + W_P + lane * PROW];
            Pq[0] = make_ulonglong2(splat2(p0), splat2(p1));
            Pq[1] = make_ulonglong2(splat2(p2), splat2(p3));
            Pq[2] = make_ulonglong2(splat2(p4), splat2(p5));
            Pq[3] = make_ulonglong2(splat2(p6), splat2(p7));
        }
        __syncwarp();                          // P visible to all lanes

        // ===== PV: p uniform, V distinct (lane = dim pair) =====
        cp_wait<1>();  __syncwarp();          // V half A landed
#pragma unroll
        for (int k = 0; k < 16; ++k) {
            const ulonglong2* Pq = (const ulonglong2*)(Pbase + k * PROW);
            ulonglong2 p01 = Pq[0], p23 = Pq[1], p45 = Pq[2], p67 = Pq[3];
            u64 v = *(const u64*)(Vb0 + k * DIM + (lane << 1));
            fma2(pv[0], p01.x, v); fma2(pv[1], p01.y, v);
            fma2(pv[2], p23.x, v); fma2(pv[3], p23.y, v);
            fma2(pv[4], p45.x, v); fma2(pv[5], p45.y, v);
            fma2(pv[6], p67.x, v); fma2(pv[7], p67.y, v);
        }
        if (t + 1 < NT) stage_k(t + 1, 0);     // A free -> next tile's K half A

        if (t + 1 < NT) { cp_wait<1>(); } else { cp_wait<0>(); }
        __syncwarp();                          // V half B landed
#pragma unroll
        for (int k = 0; k < 16; ++k) {
            const ulonglong2* Pq = (const ulonglong2*)(Pbase + (k + 16) * PROW);
            ulonglong2 p01 = Pq[0], p23 = Pq[1], p45 = Pq[2], p67 = Pq[3];
            u64 v = *(const u64*)(Vb1 + k * DIM + (lane << 1));
            fma2(pv[0], p01.x, v); fma2(pv[1], p01.y, v);
            fma2(pv[2], p23.x, v); fma2(pv[3], p23.y, v);
            fma2(pv[4], p45.x, v); fma2(pv[5], p45.y, v);
            fma2(pv[6], p67.x, v); fma2(pv[7], p67.y, v);
        }
        if (t + 1 < NT) stage_k(t + 1, 1);     // B free -> next tile's K half B
        __syncwarp();
    }

    // ================= per-warp epilogue =================
    {
        // reduce colsums across the 32 lanes (once per warp)
#pragma unroll
        for (int off = 16; off >= 1; off >>= 1) {
#pragma unroll
            for (int m = 0; m < 8; ++m)
                cs[m] += __shfl_xor_sync(0xffffffffu, cs[m], off);
        }
        float* red = &smem[OFF_W(warp)];       // reuses buffer A region
#pragma unroll
        for (int m = 0; m < 8; ++m)
            *(u64*)&red[m * 64 + (lane << 1)] = pv[m];
        if (lane == 0) {
#pragma unroll
            for (int m = 0; m < 8; ++m) red[512 + m] = cs[m];
        }
    }
    __syncthreads();

    const int pidx = (b * CPB + chunk) * NQ;
    if (tid < 8) {
        float s = 0.f;
#pragma unroll
        for (int w = 0; w < 4; ++w) s += smem[OFF_W(w) + 512 + tid];
        g_cs[pidx + tid] = s;
    }
    {
        int off = tid * 4;                    // 128 threads x float4 = 512 floats
        float4 s = make_float4(0.f, 0.f, 0.f, 0.f);
#pragma unroll
        for (int w = 0; w < 4; ++w) {
            float4 p = *(const float4*)&smem[OFF_W(w) + off];
            s.x += p.x; s.y += p.y; s.z += p.z; s.w += p.w;
        }
        *(float4*)&g_pv[(size_t)pidx * DIM + off] = s;
    }

    // ---- fused finalize: last chunk CTA of this batch ----
    __syncthreads();
    if (tid == 0) {
        __threadfence();
        unsigned old = atomicAdd(&g_cnt[b], 1u);
        s_last = (old == CPB - 1) ? 1 : 0;
    }
    __syncthreads();
    if (s_last) {
        __threadfence();
        int qm = tid >> 4, v4 = (tid & 15) << 2;
        float c0 = 0.f;
        float4 acc4 = make_float4(0.f, 0.f, 0.f, 0.f);
#pragma unroll
        for (int c = 0; c < CPB; ++c) {
            c0 += g_cs[(b * CPB + c) * NQ + qm];
            float4 p = *(const float4*)&g_pv[((size_t)(b * CPB + c) * NQ + qm) * DIM + v4];
            acc4.x += p.x; acc4.y += p.y; acc4.z += p.z; acc4.w += p.w;
        }
        float inv = 1.0f / c0;
        *(float4*)&out[((size_t)b * NQ + qm) * DIM + v4] =
            make_float4(acc4.x * inv, acc4.y * inv, acc4.z * inv, acc4.w * inv);
        if (tid == 0) g_cnt[b] = 0;   // reset for next graph replay
    }
}

extern "C" void kernel_launch(void* const* d_in, const int* in_sizes, int n_in,
                              void* d_out, int out_size) {
    const float* keys  = (const float*)d_in[0];
    const float* vals  = (const float*)d_in[1];
    const float* query = (const float*)d_in[2];
    float* out = (float*)d_out;

    cudaFuncSetAttribute(attn_fused,
                         cudaFuncAttributeMaxDynamicSharedMemorySize,
                         SMEM_FLOATS * sizeof(float));
    attn_fused<<<BQ * CPB, 128, SMEM_FLOATS * sizeof(float)>>>(keys, vals, query, out);
}